// round 12
// baseline (speedup 1.0000x reference)
#include <cuda_runtime.h>

#define NB     131072      // 32768 centers * 4 species
#define MAXE   1048576

namespace {

constexpr float PI_F   = 3.14159265358979323846f;
constexpr float NORM_F = 0.17677669529663687f;   // 1/sqrt(32)

typedef unsigned long long ull;

__device__ int    g_cnt[NB];
__device__ int    g_cur[NB];
__device__ int    g_off[NB];
__device__ float4 g_edges[MAXE];

// ---- packed fp32x2 helpers (sm_103a FFMA2 path) ----
__device__ __forceinline__ ull pack2(float lo, float hi) {
    ull r; asm("mov.b64 %0, {%1, %2};" : "=l"(r) : "f"(lo), "f"(hi)); return r;
}
__device__ __forceinline__ void unpack2(ull v, float& lo, float& hi) {
    asm("mov.b64 {%0, %1}, %2;" : "=f"(lo), "=f"(hi) : "l"(v));
}
__device__ __forceinline__ ull ffma2(ull a, ull b, ull c) {
    ull d; asm("fma.rn.f32x2 %0, %1, %2, %3;" : "=l"(d) : "l"(a), "l"(b), "l"(c));
    return d;
}

// ------------------------------------------------------------ histogram (2 edges/thread)
__global__ void k_hist(const int* __restrict__ cidx,
                       const int* __restrict__ sidx, int n) {
    int i = blockIdx.x * blockDim.x + threadIdx.x;
    int e = i * 2;
    if (e + 1 < n) {
        int2 c = *reinterpret_cast<const int2*>(&cidx[e]);
        int2 s = *reinterpret_cast<const int2*>(&sidx[e]);
        atomicAdd(&g_cnt[c.x * 4 + s.x], 1);
        atomicAdd(&g_cnt[c.y * 4 + s.y], 1);
    } else if (e < n) {
        atomicAdd(&g_cnt[cidx[e] * 4 + sidx[e]], 1);
    }
}

// ------------------------------------------------------------ fused scan
// ONE CTA, 1024 threads, each owns 128 consecutive buckets. Writes running
// offsets to g_cur (scatter cursor) and g_off (immutable starts for accum).
__global__ __launch_bounds__(1024)
void k_scan() {
    __shared__ int sm[1024];
    int t = threadIdx.x;
    int base4 = t * 32;                 // int4 index: 32 int4 = 128 buckets
    const int4* cnt4 = reinterpret_cast<const int4*>(g_cnt);

    int sum = 0;
    #pragma unroll 8
    for (int i = 0; i < 32; i++) {
        int4 v = cnt4[base4 + i];
        sum += v.x + v.y + v.z + v.w;
    }
    sm[t] = sum;
    __syncthreads();
    int mine = sum;
    #pragma unroll
    for (int off = 1; off < 1024; off <<= 1) {
        int v = (t >= off) ? sm[t - off] : 0;
        __syncthreads();
        sm[t] += v;
        __syncthreads();
    }
    int run = sm[t] - mine;             // exclusive prefix

    int4* cur4 = reinterpret_cast<int4*>(g_cur);
    int4* off4 = reinterpret_cast<int4*>(g_off);
    #pragma unroll 8
    for (int i = 0; i < 32; i++) {
        int4 v = cnt4[base4 + i];
        int4 o;
        o.x = run;
        o.y = o.x + v.x;
        o.z = o.y + v.y;
        o.w = o.z + v.z;
        run = o.w + v.w;
        cur4[base4 + i] = o;
        off4[base4 + i] = o;
    }
}

// ------------------------------------------------------------ scatter (1 edge/thread)
__global__ void k_scatter(const float* __restrict__ vec,
                          const int* __restrict__ cidx,
                          const int* __restrict__ sidx, int n) {
    int e = blockIdx.x * blockDim.x + threadIdx.x;
    if (e >= n) return;
    int b = cidx[e] * 4 + sidx[e];
    int p = atomicAdd(&g_cur[b], 1);
    g_edges[p] = make_float4(vec[3 * e], vec[3 * e + 1], vec[3 * e + 2],
                             __int_as_float(b));
}

// ------------------------------------------------------------ accumulate
// ONE WARP OWNS 8 CONSECUTIVE BUCKETS (their edges are contiguous). Edges are
// processed in coalesced 32-chunks; a running per-lane accumulator is carried
// across chunks and PLAIN-STORED on bucket change. No output atomics, no
// output memset. Launch bounds relaxed: no forced 64-reg cap (spill fix).
__global__ __launch_bounds__(256)
void k_accum(const float* __restrict__ W, float* __restrict__ out, int n) {
    __shared__ __align__(16) float sW[384];
    __shared__ __align__(16) float s_sh[8][16 * 33];   // [warp][k*33 + edge]
    __shared__ __align__(16) float s_rad[8][8 * 132];  // [warp][q*132 + edge*4 + c]

    int t = threadIdx.x, w = t >> 5, lane = t & 31;
    for (int i = t; i < 384; i += 256) sW[i] = W[i];
    __syncthreads();

    int ww = blockIdx.x * 8 + w;           // warp id, 16384 total
    int b0 = ww * 8;                       // first of 8 owned buckets
    int s0 = g_off[b0];
    int e3 = (b0 + 8 < NB) ? g_off[b0 + 8] : n;

    int myk  = lane >> 1;
    int half = lane & 1;
    int l    = (myk >= 9) ? 3 : ((myk >= 4) ? 2 : ((myk >= 1) ? 1 : 0));
    int q    = l * 2 + half;
    const float* shrow  = &s_sh[w][myk * 33];
    const float* radrow = &s_rad[w][q * 132];

    int curb = -1;
    ull a01 = 0ull, a23 = 0ull;

    for (int base = s0; base < e3; base += 32) {
        int idx = base + lane;
        int b = -1;
        float4 v = make_float4(0.f, 0.f, 0.f, 0.f);
        if (idx < e3) { v = g_edges[idx]; b = __float_as_int(v.w); }

        {
            float vx = v.x, vy = v.y, vz = v.z;
            float r2   = fmaf(vx, vx, fmaf(vy, vy, vz * vz)) + 1e-12f;
            float rinv = rsqrtf(r2);
            float r    = r2 * rinv;
            float x = vx * rinv, y = vy * rinv, z = vz * rinv;

            float a = (PI_F / 5.0f) * r;
            float sn, cs;
            __sincosf(a, &sn, &cs);
            float tt    = NORM_F * rinv;
            float two_c = 2.0f * cs;
            float phi[12];
            {
                float sm1 = 0.f, sc = sn;
                phi[0] = sc * tt;
                #pragma unroll
                for (int nn = 1; nn < 12; nn++) {
                    float s1 = fmaf(two_c, sc, -sm1);
                    sm1 = sc; sc = s1;
                    phi[nn] = sc * tt;
                }
            }

            // rad per l with packed f32x2 FMA (W rows are uniform smem loads)
            #pragma unroll
            for (int ll = 0; ll < 4; ll++) {
                ull r01 = 0ull, r23 = 0ull, r45 = 0ull, r67 = 0ull;
                #pragma unroll
                for (int bb = 0; bb < 12; bb++) {
                    ull pp = pack2(phi[bb], phi[bb]);
                    ulonglong2 w_lo = reinterpret_cast<const ulonglong2*>(sW)[(ll * 96 + bb * 8) / 4];
                    ulonglong2 w_hi = reinterpret_cast<const ulonglong2*>(sW)[(ll * 96 + bb * 8) / 4 + 1];
                    r01 = ffma2(pp, w_lo.x, r01);
                    r23 = ffma2(pp, w_lo.y, r23);
                    r45 = ffma2(pp, w_hi.x, r45);
                    r67 = ffma2(pp, w_hi.y, r67);
                }
                *reinterpret_cast<ulonglong2*>(&s_rad[w][(ll * 2 + 0) * 132 + lane * 4]) =
                    make_ulonglong2(r01, r23);
                *reinterpret_cast<ulonglong2*>(&s_rad[w][(ll * 2 + 1) * 132 + lane * 4]) =
                    make_ulonglong2(r45, r67);
            }

            float x2 = x * x, y2 = y * y, z2 = z * z;
            float* sr = &s_sh[w][lane];
            sr[0  * 33] = 0.28209479177387814f;
            sr[1  * 33] = 0.4886025119029199f * y;
            sr[2  * 33] = 0.4886025119029199f * z;
            sr[3  * 33] = 0.4886025119029199f * x;
            sr[4  * 33] = 1.0925484305920792f * x * y;
            sr[5  * 33] = 1.0925484305920792f * y * z;
            sr[6  * 33] = 0.31539156525252005f * fmaf(3.0f, z2, -1.0f);
            sr[7  * 33] = 1.0925484305920792f * x * z;
            sr[8  * 33] = 0.5462742152960396f * (x2 - y2);
            sr[9  * 33] = 0.5900435899266435f * y * fmaf(3.0f, x2, -y2);
            sr[10 * 33] = 2.890611442640554f  * x * y * z;
            sr[11 * 33] = 0.4570457994644658f * y * fmaf(5.0f, z2, -1.0f);
            sr[12 * 33] = 0.3731763325901154f * z * fmaf(5.0f, z2, -3.0f);
            sr[13 * 33] = 0.4570457994644658f * x * fmaf(5.0f, z2, -1.0f);
            sr[14 * 33] = 1.445305721320277f  * z * (x2 - y2);
            sr[15 * 33] = 0.5900435899266435f * x * (x2 - y2);
        }
        __syncwarp();

        // segment detection over sorted bucket ids (ascending within chunk)
        int b_up = __shfl_up_sync(0xffffffffu, b, 1);
        bool head = (lane == 0) || (b != b_up);
        unsigned hm = __ballot_sync(0xffffffffu, head);

        unsigned m = hm;
        while (m) {
            int s = __ffs(m) - 1;
            m &= m - 1;
            int e2 = m ? (__ffs(m) - 1) : 32;
            int bs = __shfl_sync(0xffffffffu, b, s);
            if (bs >= 0) {
                if (bs != curb) {
                    if (curb >= 0) {
                        float ax, ay, az, aw;
                        unpack2(a01, ax, ay);
                        unpack2(a23, az, aw);
                        float* p = out + ((curb >> 2) * 512 + myk * 32 + (curb & 3) * 8 + half * 4);
                        *reinterpret_cast<float4*>(p) = make_float4(ax, ay, az, aw);
                    }
                    curb = bs;
                    a01 = 0ull; a23 = 0ull;
                }
                for (int i = s; i < e2; i++) {
                    float sk = shrow[i];
                    ull shp = pack2(sk, sk);
                    ulonglong2 rr = *reinterpret_cast<const ulonglong2*>(&radrow[i * 4]);
                    a01 = ffma2(shp, rr.x, a01);
                    a23 = ffma2(shp, rr.y, a23);
                }
            }
        }
        __syncwarp();
    }

    // final flush
    if (curb >= 0) {
        float ax, ay, az, aw;
        unpack2(a01, ax, ay);
        unpack2(a23, az, aw);
        float* p = out + ((curb >> 2) * 512 + myk * 32 + (curb & 3) * 8 + half * 4);
        *reinterpret_cast<float4*>(p) = make_float4(ax, ay, az, aw);
    }

    // empty buckets: write zeros exactly once
    bool is_empty = false;
    if (lane < 8) {
        int bkt = b0 + lane;
        int st  = g_off[bkt];
        int en  = (bkt + 1 < NB) ? g_off[bkt + 1] : n;
        is_empty = (st == en);
    }
    unsigned em = __ballot_sync(0xffffffffu, is_empty);
    while (em) {
        int j = __ffs(em) - 1;
        em &= em - 1;
        int bkt = b0 + j;
        float* p = out + ((bkt >> 2) * 512 + myk * 32 + (bkt & 3) * 8 + half * 4);
        *reinterpret_cast<float4*>(p) = make_float4(0.f, 0.f, 0.f, 0.f);
    }
}

} // namespace

extern "C" void kernel_launch(void* const* d_in, const int* in_sizes, int n_in,
                              void* d_out, int out_size)
{
    const float* vectors = (const float*)d_in[0];
    const float* W       = (const float*)d_in[1];
    const int*   cidx    = (const int*)d_in[2];
    const int*   sidx    = (const int*)d_in[3];
    float*       out     = (float*)d_out;

    int n_edges = in_sizes[2];

    static void* cnt_ptr = nullptr;
    if (!cnt_ptr) cudaGetSymbolAddress(&cnt_ptr, g_cnt);

    // 4 kernels/iter: hist(1), scan(2), scatter(3), accum(4)
    // -> ncu (which consistently captures the 4th kernel) profiles k_accum.
    cudaMemsetAsync(cnt_ptr, 0, NB * sizeof(int), 0);
    k_hist<<<(n_edges / 2 + 255) / 256, 256>>>(cidx, sidx, n_edges);
    k_scan<<<1, 1024>>>();
    k_scatter<<<(n_edges + 255) / 256, 256>>>(vectors, cidx, sidx, n_edges);
    k_accum<<<NB / 8 / 8, 256>>>(W, out, n_edges);   // 16384 warps, 8 buckets each
}

// round 14
// speedup vs baseline: 1.8119x; 1.8119x over previous
#include <cuda_runtime.h>

#define NB     131072      // 32768 centers * 4 species
#define MAXE   1048576

namespace {

constexpr float PI_F   = 3.14159265358979323846f;
constexpr float NORM_F = 0.17677669529663687f;   // 1/sqrt(32)

typedef unsigned long long ull;

__device__ int    g_cnt[NB];
__device__ int    g_cur[NB];
__device__ int    g_off[NB];
__device__ int    g_blk[128];
__device__ float4 g_edges[MAXE];

// ---- packed fp32x2 helpers (sm_103a FFMA2 path) ----
__device__ __forceinline__ ull pack2(float lo, float hi) {
    ull r; asm("mov.b64 %0, {%1, %2};" : "=l"(r) : "f"(lo), "f"(hi)); return r;
}
__device__ __forceinline__ void unpack2(ull v, float& lo, float& hi) {
    asm("mov.b64 {%0, %1}, %2;" : "=f"(lo), "=f"(hi) : "l"(v));
}
__device__ __forceinline__ ull ffma2(ull a, ull b, ull c) {
    ull d; asm("fma.rn.f32x2 %0, %1, %2, %3;" : "=l"(d) : "l"(a), "l"(b), "l"(c));
    return d;
}

// ------------------------------------------------------------ histogram (2 edges/thread)
__global__ void k_hist(const int* __restrict__ cidx,
                       const int* __restrict__ sidx, int n) {
    int i = blockIdx.x * blockDim.x + threadIdx.x;
    int e = i * 2;
    if (e + 1 < n) {
        int2 c = *reinterpret_cast<const int2*>(&cidx[e]);
        int2 s = *reinterpret_cast<const int2*>(&sidx[e]);
        atomicAdd(&g_cnt[c.x * 4 + s.x], 1);
        atomicAdd(&g_cnt[c.y * 4 + s.y], 1);
    } else if (e < n) {
        atomicAdd(&g_cnt[cidx[e] * 4 + sidx[e]], 1);
    }
}

// ------------------------------------------------------------ scan step A
__global__ void k_scanA() {            // 128 blocks x 256 threads
    __shared__ int sm[256];
    int t = threadIdx.x, blk = blockIdx.x;
    int base = blk * 1024 + t * 4;
    int4 c = *reinterpret_cast<const int4*>(&g_cnt[base]);
    int s = c.x + c.y + c.z + c.w;
    sm[t] = s;
    __syncthreads();
    #pragma unroll
    for (int off = 1; off < 256; off <<= 1) {
        int v = (t >= off) ? sm[t - off] : 0;
        __syncthreads();
        sm[t] += v;
        __syncthreads();
    }
    int ex = sm[t] - s;                // exclusive within CTA
    int4 o;
    o.x = ex; o.y = ex + c.x; o.z = o.y + c.y; o.w = o.z + c.z;
    *reinterpret_cast<int4*>(&g_cur[base]) = o;
    if (t == 255) g_blk[blk] = sm[255];
}

// ------------------------------------------------------------ scan step B+C fused
__global__ void k_scanC() {            // 128 blocks x 256 threads
    __shared__ int s_wsum[8];
    __shared__ int s_off;
    int t = threadIdx.x, blk = blockIdx.x;

    int contrib = (t < 128 && t < blk) ? g_blk[t] : 0;
    #pragma unroll
    for (int o = 16; o; o >>= 1)
        contrib += __shfl_down_sync(0xffffffffu, contrib, o);
    if ((t & 31) == 0) s_wsum[t >> 5] = contrib;
    __syncthreads();
    if (t == 0) {
        int a = 0;
        #pragma unroll
        for (int i = 0; i < 8; i++) a += s_wsum[i];
        s_off = a;
    }
    __syncthreads();
    int off = s_off;

    int i = blk * 256 + t;
    int4 v = *reinterpret_cast<int4*>(&g_cur[i * 4]);
    v.x += off; v.y += off; v.z += off; v.w += off;
    *reinterpret_cast<int4*>(&g_cur[i * 4]) = v;   // running cursor (scatter)
    *reinterpret_cast<int4*>(&g_off[i * 4]) = v;   // immutable starts (accum)
}

// ------------------------------------------------------------ scatter (1 edge/thread)
__global__ void k_scatter(const float* __restrict__ vec,
                          const int* __restrict__ cidx,
                          const int* __restrict__ sidx, int n) {
    int e = blockIdx.x * blockDim.x + threadIdx.x;
    if (e >= n) return;
    int b = cidx[e] * 4 + sidx[e];
    int p = atomicAdd(&g_cur[b], 1);
    g_edges[p] = make_float4(vec[3 * e], vec[3 * e + 1], vec[3 * e + 2],
                             __int_as_float(b));
}

// ------------------------------------------------------------ accumulate
// ONE WARP OWNS 8 CONSECUTIVE BUCKETS. MIO fix vs R12: the radial projection
// holds W in REGISTERS (each lane owns one q-row = 12 float4 = 48 regs, loaded
// once) instead of re-reading 1.5KB of W from smem per edge. Edge lanes stage
// phi[12] to smem (stride 12 -> conflict-free for gen reads); gen lanes
// (q = lane>>2, grp = lane&3) produce rad rows for 8 edges each.
__global__ __launch_bounds__(256)
void k_accum(const float* __restrict__ W, float* __restrict__ out, int n) {
    __shared__ __align__(16) float s_phi[8][32 * 12];  // [warp][edge*12 + b]
    __shared__ __align__(16) float s_sh[8][16 * 33];   // [warp][k*33 + edge]
    __shared__ __align__(16) float s_rad[8][8 * 132];  // [warp][q*132 + edge*4 + c]

    int t = threadIdx.x, w = t >> 5, lane = t & 31;

    // --- per-lane W slice in registers: q_gen = lane>>2 ---
    int q_gen = lane >> 2;                 // 0..7
    int grp   = lane & 3;                  // 0..3
    {
    }
    ull w01[12], w23[12];
    {
        int lg   = q_gen >> 1;             // l of this q-row
        int hf   = q_gen & 1;              // half of this q-row
        const float4* Wp = reinterpret_cast<const float4*>(W);
        #pragma unroll
        for (int b = 0; b < 12; b++) {
            float4 wv = Wp[(lg * 96 + b * 8 + hf * 4) >> 2];
            w01[b] = pack2(wv.x, wv.y);
            w23[b] = pack2(wv.z, wv.w);
        }
    }

    int ww = blockIdx.x * 8 + w;           // warp id, 16384 total
    int b0 = ww * 8;                       // first of 8 owned buckets
    int s0 = g_off[b0];
    int e3 = (b0 + 8 < NB) ? g_off[b0 + 8] : n;

    int myk  = lane >> 1;
    int half = lane & 1;
    int l    = (myk >= 9) ? 3 : ((myk >= 4) ? 2 : ((myk >= 1) ? 1 : 0));
    int q    = l * 2 + half;
    const float* shrow  = &s_sh[w][myk * 33];
    const float* radrow = &s_rad[w][q * 132];

    int curb = -1;
    ull a01 = 0ull, a23 = 0ull;

    for (int base = s0; base < e3; base += 32) {
        int idx = base + lane;
        int b = -1;
        float4 v = make_float4(0.f, 0.f, 0.f, 0.f);
        if (idx < e3) { v = g_edges[idx]; b = __float_as_int(v.w); }

        // ---- stage phi + sh for own edge ----
        {
            float vx = v.x, vy = v.y, vz = v.z;
            float r2   = fmaf(vx, vx, fmaf(vy, vy, vz * vz)) + 1e-12f;
            float rinv = rsqrtf(r2);
            float r    = r2 * rinv;
            float x = vx * rinv, y = vy * rinv, z = vz * rinv;

            float a = (PI_F / 5.0f) * r;
            float sn, cs;
            __sincosf(a, &sn, &cs);
            float tt    = NORM_F * rinv;
            float two_c = 2.0f * cs;
            float phi[12];
            {
                float sm1 = 0.f, sc = sn;
                phi[0] = sc * tt;
                #pragma unroll
                for (int nn = 1; nn < 12; nn++) {
                    float s1 = fmaf(two_c, sc, -sm1);
                    sm1 = sc; sc = s1;
                    phi[nn] = sc * tt;
                }
            }
            float* pp = &s_phi[w][lane * 12];
            *reinterpret_cast<float4*>(pp + 0) = make_float4(phi[0], phi[1], phi[2],  phi[3]);
            *reinterpret_cast<float4*>(pp + 4) = make_float4(phi[4], phi[5], phi[6],  phi[7]);
            *reinterpret_cast<float4*>(pp + 8) = make_float4(phi[8], phi[9], phi[10], phi[11]);

            float x2 = x * x, y2 = y * y, z2 = z * z;
            float* sr = &s_sh[w][lane];
            sr[0  * 33] = 0.28209479177387814f;
            sr[1  * 33] = 0.4886025119029199f * y;
            sr[2  * 33] = 0.4886025119029199f * z;
            sr[3  * 33] = 0.4886025119029199f * x;
            sr[4  * 33] = 1.0925484305920792f * x * y;
            sr[5  * 33] = 1.0925484305920792f * y * z;
            sr[6  * 33] = 0.31539156525252005f * fmaf(3.0f, z2, -1.0f);
            sr[7  * 33] = 1.0925484305920792f * x * z;
            sr[8  * 33] = 0.5462742152960396f * (x2 - y2);
            sr[9  * 33] = 0.5900435899266435f * y * fmaf(3.0f, x2, -y2);
            sr[10 * 33] = 2.890611442640554f  * x * y * z;
            sr[11 * 33] = 0.4570457994644658f * y * fmaf(5.0f, z2, -1.0f);
            sr[12 * 33] = 0.3731763325901154f * z * fmaf(5.0f, z2, -3.0f);
            sr[13 * 33] = 0.4570457994644658f * x * fmaf(5.0f, z2, -1.0f);
            sr[14 * 33] = 1.445305721320277f  * z * (x2 - y2);
            sr[15 * 33] = 0.5900435899266435f * x * (x2 - y2);
        }
        __syncwarp();

        // ---- rad generation: lane (q_gen, grp) does edges e = 4j+grp ----
        #pragma unroll
        for (int j = 0; j < 8; j++) {
            int e = 4 * j + grp;
            const float* pp = &s_phi[w][e * 12];
            float4 p0 = *reinterpret_cast<const float4*>(pp + 0);
            float4 p1 = *reinterpret_cast<const float4*>(pp + 4);
            float4 p2 = *reinterpret_cast<const float4*>(pp + 8);
            ull r01 = 0ull, r23 = 0ull;
            float ph[12] = {p0.x, p0.y, p0.z, p0.w,
                            p1.x, p1.y, p1.z, p1.w,
                            p2.x, p2.y, p2.z, p2.w};
            #pragma unroll
            for (int bb = 0; bb < 12; bb++) {
                ull sp = pack2(ph[bb], ph[bb]);
                r01 = ffma2(sp, w01[bb], r01);
                r23 = ffma2(sp, w23[bb], r23);
            }
            *reinterpret_cast<ulonglong2*>(&s_rad[w][q_gen * 132 + e * 4]) =
                make_ulonglong2(r01, r23);
        }
        __syncwarp();

        // ---- segment detection + reduce over sorted bucket ids ----
        int b_up = __shfl_up_sync(0xffffffffu, b, 1);
        bool head = (lane == 0) || (b != b_up);
        unsigned hm = __ballot_sync(0xffffffffu, head);

        unsigned m = hm;
        while (m) {
            int s = __ffs(m) - 1;
            m &= m - 1;
            int e2 = m ? (__ffs(m) - 1) : 32;
            int bs = __shfl_sync(0xffffffffu, b, s);
            if (bs >= 0) {
                if (bs != curb) {
                    if (curb >= 0) {
                        float ax, ay, az, aw;
                        unpack2(a01, ax, ay);
                        unpack2(a23, az, aw);
                        float* p = out + ((curb >> 2) * 512 + myk * 32 + (curb & 3) * 8 + half * 4);
                        *reinterpret_cast<float4*>(p) = make_float4(ax, ay, az, aw);
                    }
                    curb = bs;
                    a01 = 0ull; a23 = 0ull;
                }
                for (int i = s; i < e2; i++) {
                    float sk = shrow[i];
                    ull shp = pack2(sk, sk);
                    ulonglong2 rr = *reinterpret_cast<const ulonglong2*>(&radrow[i * 4]);
                    a01 = ffma2(shp, rr.x, a01);
                    a23 = ffma2(shp, rr.y, a23);
                }
            }
        }
        __syncwarp();
    }

    // final flush
    if (curb >= 0) {
        float ax, ay, az, aw;
        unpack2(a01, ax, ay);
        unpack2(a23, az, aw);
        float* p = out + ((curb >> 2) * 512 + myk * 32 + (curb & 3) * 8 + half * 4);
        *reinterpret_cast<float4*>(p) = make_float4(ax, ay, az, aw);
    }

    // empty buckets: write zeros exactly once
    bool is_empty = false;
    if (lane < 8) {
        int bkt = b0 + lane;
        int st  = g_off[bkt];
        int en  = (bkt + 1 < NB) ? g_off[bkt + 1] : n;
        is_empty = (st == en);
    }
    unsigned em = __ballot_sync(0xffffffffu, is_empty);
    while (em) {
        int j = __ffs(em) - 1;
        em &= em - 1;
        int bkt = b0 + j;
        float* p = out + ((bkt >> 2) * 512 + myk * 32 + (bkt & 3) * 8 + half * 4);
        *reinterpret_cast<float4*>(p) = make_float4(0.f, 0.f, 0.f, 0.f);
    }
}

} // namespace

extern "C" void kernel_launch(void* const* d_in, const int* in_sizes, int n_in,
                              void* d_out, int out_size)
{
    const float* vectors = (const float*)d_in[0];
    const float* W       = (const float*)d_in[1];
    const int*   cidx    = (const int*)d_in[2];
    const int*   sidx    = (const int*)d_in[3];
    float*       out     = (float*)d_out;

    int n_edges = in_sizes[2];

    static void* cnt_ptr = nullptr;
    if (!cnt_ptr) cudaGetSymbolAddress(&cnt_ptr, g_cnt);

    cudaMemsetAsync(cnt_ptr, 0, NB * sizeof(int), 0);
    k_hist<<<(n_edges / 2 + 255) / 256, 256>>>(cidx, sidx, n_edges);
    k_scanA<<<128, 256>>>();
    k_scanC<<<128, 256>>>();
    k_scatter<<<(n_edges + 255) / 256, 256>>>(vectors, cidx, sidx, n_edges);
    k_accum<<<NB / 8 / 8, 256>>>(W, out, n_edges);   // 16384 warps, 8 buckets each
}

// round 15
// speedup vs baseline: 1.8417x; 1.0164x over previous
#include <cuda_runtime.h>

#define NB     131072      // 32768 centers * 4 species
#define MAXE   1048576

namespace {

constexpr float PI_F   = 3.14159265358979323846f;
constexpr float NORM_F = 0.17677669529663687f;   // 1/sqrt(32)

typedef unsigned long long ull;

__device__ int    g_cnt[NB];
__device__ int    g_cur[NB];
__device__ int    g_off[NB];
__device__ int    g_blk[128];
__device__ float4 g_edges[MAXE];

// ---- packed fp32x2 helpers ----
__device__ __forceinline__ ull pack2(float lo, float hi) {
    ull r; asm("mov.b64 %0, {%1, %2};" : "=l"(r) : "f"(lo), "f"(hi)); return r;
}
__device__ __forceinline__ void unpack2(ull v, float& lo, float& hi) {
    asm("mov.b64 {%0, %1}, %2;" : "=f"(lo), "=f"(hi) : "l"(v));
}
__device__ __forceinline__ ull ffma2(ull a, ull b, ull c) {
    ull d; asm("fma.rn.f32x2 %0, %1, %2, %3;" : "=l"(d) : "l"(a), "l"(b), "l"(c));
    return d;
}

// ------------------------------------------------------------ histogram (2 edges/thread)
__global__ void k_hist(const int* __restrict__ cidx,
                       const int* __restrict__ sidx, int n) {
    int i = blockIdx.x * blockDim.x + threadIdx.x;
    int e = i * 2;
    if (e + 1 < n) {
        int2 c = *reinterpret_cast<const int2*>(&cidx[e]);
        int2 s = *reinterpret_cast<const int2*>(&sidx[e]);
        atomicAdd(&g_cnt[c.x * 4 + s.x], 1);
        atomicAdd(&g_cnt[c.y * 4 + s.y], 1);
    } else if (e < n) {
        atomicAdd(&g_cnt[cidx[e] * 4 + sidx[e]], 1);
    }
}

// ------------------------------------------------------------ scan step A
__global__ void k_scanA() {            // 128 blocks x 256 threads
    __shared__ int sm[256];
    int t = threadIdx.x, blk = blockIdx.x;
    int base = blk * 1024 + t * 4;
    int4 c = *reinterpret_cast<const int4*>(&g_cnt[base]);
    int s = c.x + c.y + c.z + c.w;
    sm[t] = s;
    __syncthreads();
    #pragma unroll
    for (int off = 1; off < 256; off <<= 1) {
        int v = (t >= off) ? sm[t - off] : 0;
        __syncthreads();
        sm[t] += v;
        __syncthreads();
    }
    int ex = sm[t] - s;                // exclusive within CTA
    int4 o;
    o.x = ex; o.y = ex + c.x; o.z = o.y + c.y; o.w = o.z + c.z;
    *reinterpret_cast<int4*>(&g_cur[base]) = o;
    if (t == 255) g_blk[blk] = sm[255];
}

// ------------------------------------------------------------ scan step B+C fused
__global__ void k_scanC() {            // 128 blocks x 256 threads
    __shared__ int s_wsum[8];
    __shared__ int s_off;
    int t = threadIdx.x, blk = blockIdx.x;

    int contrib = (t < 128 && t < blk) ? g_blk[t] : 0;
    #pragma unroll
    for (int o = 16; o; o >>= 1)
        contrib += __shfl_down_sync(0xffffffffu, contrib, o);
    if ((t & 31) == 0) s_wsum[t >> 5] = contrib;
    __syncthreads();
    if (t == 0) {
        int a = 0;
        #pragma unroll
        for (int i = 0; i < 8; i++) a += s_wsum[i];
        s_off = a;
    }
    __syncthreads();
    int off = s_off;

    int i = blk * 256 + t;
    int4 v = *reinterpret_cast<int4*>(&g_cur[i * 4]);
    v.x += off; v.y += off; v.z += off; v.w += off;
    *reinterpret_cast<int4*>(&g_cur[i * 4]) = v;   // running cursor (scatter)
    *reinterpret_cast<int4*>(&g_off[i * 4]) = v;   // immutable starts (accum)
}

// ------------------------------------------------------------ scatter (1 edge/thread)
__global__ void k_scatter(const float* __restrict__ vec,
                          const int* __restrict__ cidx,
                          const int* __restrict__ sidx, int n) {
    int e = blockIdx.x * blockDim.x + threadIdx.x;
    if (e >= n) return;
    int b = cidx[e] * 4 + sidx[e];
    int p = atomicAdd(&g_cur[b], 1);
    g_edges[p] = make_float4(vec[3 * e], vec[3 * e + 1], vec[3 * e + 2],
                             __int_as_float(b));
}

// ------------------------------------------------------------ accumulate
// ONE WARP OWNS 8 CONSECUTIVE BUCKETS. Per-bucket MOMENT accumulation:
//   lane (k = lane&15, nh = lane>>4) accumulates m[b] = sum_e sh[k]*phi[b]
//   (12 floats packed in 6 ull), then contracts with a 48-reg W slice at
//   bucket change and emits ONE STG.128 (its 4 outputs). The warp's 32 lanes
//   cover the bucket's full 512B, written exactly once. No output atomics,
//   no output memset, no rad materialization.
__global__ __launch_bounds__(256)
void k_accum(const float* __restrict__ W, float* __restrict__ out, int n) {
    __shared__ __align__(16) float s_phi[8][32 * 12];  // [warp][edge*12 + b]
    __shared__ __align__(16) float s_sh[8][16 * 33];   // [warp][k*33 + edge]

    int t = threadIdx.x, w = t >> 5, lane = t & 31;
    int k  = lane & 15;
    int nh = lane >> 4;                    // n-half: outputs n = nh*4 .. nh*4+3
    int l  = (k >= 9) ? 3 : ((k >= 4) ? 2 : ((k >= 1) ? 1 : 0));

    // W slice in registers: W[l][b][nh*4 .. nh*4+3] as 2 packed pairs per b
    ull wreg[12][2];
    {
        const float4* Wp = reinterpret_cast<const float4*>(W);
        #pragma unroll
        for (int b = 0; b < 12; b++) {
            float4 wv = Wp[(l * 96 + b * 8 + nh * 4) >> 2];
            wreg[b][0] = pack2(wv.x, wv.y);
            wreg[b][1] = pack2(wv.z, wv.w);
        }
    }

    int ww = blockIdx.x * 8 + w;           // warp id, 16384 total
    int b0 = ww * 8;                       // first of 8 owned buckets
    int s0 = g_off[b0];
    int e3 = (b0 + 8 < NB) ? g_off[b0 + 8] : n;

    const float* shrow = &s_sh[w][k * 33];

    int curb = -1;
    ull m[6];
    #pragma unroll
    for (int j = 0; j < 6; j++) m[j] = 0ull;

    for (int base = s0; base < e3; base += 32) {
        int idx = base + lane;
        int b = -1;
        float4 v = make_float4(0.f, 0.f, 0.f, 0.f);
        if (idx < e3) { v = g_edges[idx]; b = __float_as_int(v.w); }

        // ---- stage phi + sh for own edge ----
        {
            float vx = v.x, vy = v.y, vz = v.z;
            float r2   = fmaf(vx, vx, fmaf(vy, vy, vz * vz)) + 1e-12f;
            float rinv = rsqrtf(r2);
            float r    = r2 * rinv;
            float x = vx * rinv, y = vy * rinv, z = vz * rinv;

            float a = (PI_F / 5.0f) * r;
            float sn, cs;
            __sincosf(a, &sn, &cs);
            float tt    = NORM_F * rinv;
            float two_c = 2.0f * cs;
            float phi[12];
            {
                float sm1 = 0.f, sc = sn;
                phi[0] = sc * tt;
                #pragma unroll
                for (int nn = 1; nn < 12; nn++) {
                    float s1 = fmaf(two_c, sc, -sm1);
                    sm1 = sc; sc = s1;
                    phi[nn] = sc * tt;
                }
            }
            float* pp = &s_phi[w][lane * 12];
            *reinterpret_cast<float4*>(pp + 0) = make_float4(phi[0], phi[1], phi[2],  phi[3]);
            *reinterpret_cast<float4*>(pp + 4) = make_float4(phi[4], phi[5], phi[6],  phi[7]);
            *reinterpret_cast<float4*>(pp + 8) = make_float4(phi[8], phi[9], phi[10], phi[11]);

            float x2 = x * x, y2 = y * y, z2 = z * z;
            float* sr = &s_sh[w][lane];
            sr[0  * 33] = 0.28209479177387814f;
            sr[1  * 33] = 0.4886025119029199f * y;
            sr[2  * 33] = 0.4886025119029199f * z;
            sr[3  * 33] = 0.4886025119029199f * x;
            sr[4  * 33] = 1.0925484305920792f * x * y;
            sr[5  * 33] = 1.0925484305920792f * y * z;
            sr[6  * 33] = 0.31539156525252005f * fmaf(3.0f, z2, -1.0f);
            sr[7  * 33] = 1.0925484305920792f * x * z;
            sr[8  * 33] = 0.5462742152960396f * (x2 - y2);
            sr[9  * 33] = 0.5900435899266435f * y * fmaf(3.0f, x2, -y2);
            sr[10 * 33] = 2.890611442640554f  * x * y * z;
            sr[11 * 33] = 0.4570457994644658f * y * fmaf(5.0f, z2, -1.0f);
            sr[12 * 33] = 0.3731763325901154f * z * fmaf(5.0f, z2, -3.0f);
            sr[13 * 33] = 0.4570457994644658f * x * fmaf(5.0f, z2, -1.0f);
            sr[14 * 33] = 1.445305721320277f  * z * (x2 - y2);
            sr[15 * 33] = 0.5900435899266435f * x * (x2 - y2);
        }
        __syncwarp();

        // ---- segment detection + moment accumulation ----
        int b_up = __shfl_up_sync(0xffffffffu, b, 1);
        bool head = (lane == 0) || (b != b_up);
        unsigned hm = __ballot_sync(0xffffffffu, head);

        unsigned msk = hm;
        while (msk) {
            int s = __ffs(msk) - 1;
            msk &= msk - 1;
            int e2 = msk ? (__ffs(msk) - 1) : 32;
            int bs = __shfl_sync(0xffffffffu, b, s);
            if (bs >= 0) {
                if (bs != curb) {
                    if (curb >= 0) {
                        // flush: contract m with W slice, one STG.128
                        float mv[12];
                        #pragma unroll
                        for (int j = 0; j < 6; j++) unpack2(m[j], mv[2 * j], mv[2 * j + 1]);
                        ull po0 = 0ull, po1 = 0ull;
                        #pragma unroll
                        for (int bb = 0; bb < 12; bb++) {
                            ull sp = pack2(mv[bb], mv[bb]);
                            po0 = ffma2(sp, wreg[bb][0], po0);
                            po1 = ffma2(sp, wreg[bb][1], po1);
                        }
                        float f0, f1, f2, f3;
                        unpack2(po0, f0, f1);
                        unpack2(po1, f2, f3);
                        float* p = out + ((curb >> 2) * 512 + k * 32 + (curb & 3) * 8 + nh * 4);
                        *reinterpret_cast<float4*>(p) = make_float4(f0, f1, f2, f3);
                    }
                    curb = bs;
                    #pragma unroll
                    for (int j = 0; j < 6; j++) m[j] = 0ull;
                }
                for (int i = s; i < e2; i++) {
                    float sk = shrow[i];
                    ull skp = pack2(sk, sk);
                    const ulonglong2* pp =
                        reinterpret_cast<const ulonglong2*>(&s_phi[w][i * 12]);
                    ulonglong2 q0 = pp[0];
                    ulonglong2 q1 = pp[1];
                    ulonglong2 q2 = pp[2];
                    m[0] = ffma2(skp, q0.x, m[0]);
                    m[1] = ffma2(skp, q0.y, m[1]);
                    m[2] = ffma2(skp, q1.x, m[2]);
                    m[3] = ffma2(skp, q1.y, m[3]);
                    m[4] = ffma2(skp, q2.x, m[4]);
                    m[5] = ffma2(skp, q2.y, m[5]);
                }
            }
        }
        __syncwarp();
    }

    // final flush
    if (curb >= 0) {
        float mv[12];
        #pragma unroll
        for (int j = 0; j < 6; j++) unpack2(m[j], mv[2 * j], mv[2 * j + 1]);
        ull po0 = 0ull, po1 = 0ull;
        #pragma unroll
        for (int bb = 0; bb < 12; bb++) {
            ull sp = pack2(mv[bb], mv[bb]);
            po0 = ffma2(sp, wreg[bb][0], po0);
            po1 = ffma2(sp, wreg[bb][1], po1);
        }
        float f0, f1, f2, f3;
        unpack2(po0, f0, f1);
        unpack2(po1, f2, f3);
        float* p = out + ((curb >> 2) * 512 + k * 32 + (curb & 3) * 8 + nh * 4);
        *reinterpret_cast<float4*>(p) = make_float4(f0, f1, f2, f3);
    }

    // empty buckets: write zeros exactly once (each lane its STG.128)
    bool is_empty = false;
    if (lane < 8) {
        int bkt = b0 + lane;
        int st  = g_off[bkt];
        int en  = (bkt + 1 < NB) ? g_off[bkt + 1] : n;
        is_empty = (st == en);
    }
    unsigned em = __ballot_sync(0xffffffffu, is_empty);
    while (em) {
        int j = __ffs(em) - 1;
        em &= em - 1;
        int bkt = b0 + j;
        float* p = out + ((bkt >> 2) * 512 + k * 32 + (bkt & 3) * 8 + nh * 4);
        *reinterpret_cast<float4*>(p) = make_float4(0.f, 0.f, 0.f, 0.f);
    }
}

} // namespace

extern "C" void kernel_launch(void* const* d_in, const int* in_sizes, int n_in,
                              void* d_out, int out_size)
{
    const float* vectors = (const float*)d_in[0];
    const float* W       = (const float*)d_in[1];
    const int*   cidx    = (const int*)d_in[2];
    const int*   sidx    = (const int*)d_in[3];
    float*       out     = (float*)d_out;

    int n_edges = in_sizes[2];

    static void* cnt_ptr = nullptr;
    if (!cnt_ptr) cudaGetSymbolAddress(&cnt_ptr, g_cnt);

    cudaMemsetAsync(cnt_ptr, 0, NB * sizeof(int), 0);
    k_hist<<<(n_edges / 2 + 255) / 256, 256>>>(cidx, sidx, n_edges);
    k_scanA<<<128, 256>>>();
    k_scanC<<<128, 256>>>();
    k_scatter<<<(n_edges + 255) / 256, 256>>>(vectors, cidx, sidx, n_edges);
    k_accum<<<NB / 8 / 8, 256>>>(W, out, n_edges);   // 16384 warps, 8 buckets each
}